// round 2
// baseline (speedup 1.0000x reference)
#include <cuda_runtime.h>
#include <cstdint>

// HighOrderFactorizationMachineModel: BATCH=16384, F=20 fields (dim 50000 each),
// EMBED_DIM=16, ORDER=3. emb_table row = 32 floats: [0:16) order-2 dims,
// [16:32) order-3 dims. Closed forms via power sums (Newton identities):
//   e2 = (p1^2 - p2)/2
//   e3 = (p1^3 - 3 p1 p2 + 2 p3)/6
//
// TWO samples per warp, gathers interleaved -> ~40 outstanding 128B-line
// loads per warp (latency hiding), and grid = 1024 blocks -> single wave
// on 148 SMs (no wave-quantization tail).
// Lane l owns row element l -> every emb gather is one coalesced 128B line.

#define FM_BATCH 16384
#define FM_F 20
#define FM_FIELD_DIM 50000

__global__ __launch_bounds__(256)
void fm_ho_kernel(const int* __restrict__ x,
                  const float* __restrict__ emb,
                  const float* __restrict__ lin,
                  const float* __restrict__ bias,
                  float* __restrict__ out)
{
    const int warp = (blockIdx.x * blockDim.x + threadIdx.x) >> 5;
    const int lane = threadIdx.x & 31;

    const int sA = 2 * warp;        // first sample
    const int sB = 2 * warp + 1;    // second sample

    // Lane f (<20) holds the global table index for field f of each sample.
    int gA = 0, gB = 0;
    float linA = 0.0f, linB = 0.0f;
    if (lane < FM_F) {
        const int off = lane * FM_FIELD_DIM;
        gA = x[sA * FM_F + lane] + off;
        gB = x[sB * FM_F + lane] + off;
        linA = __ldg(&lin[gA]);
        linB = __ldg(&lin[gB]);
    }

    float p1a = 0.0f, p2a = 0.0f, p3a = 0.0f;
    float p1b = 0.0f, p2b = 0.0f, p3b = 0.0f;

    #pragma unroll
    for (int f = 0; f < FM_F; f++) {
        const int ia = __shfl_sync(0xffffffffu, gA, f);
        const int ib = __shfl_sync(0xffffffffu, gB, f);
        const float va = __ldg(&emb[(long)ia * 32 + lane]);
        const float vb = __ldg(&emb[(long)ib * 32 + lane]);
        const float va2 = va * va;
        const float vb2 = vb * vb;
        p1a += va;  p2a += va2;  p3a += va2 * va;
        p1b += vb;  p2b += vb2;  p3b += vb2 * vb;
    }

    // Lanes 0..15: order-2 dims. Lanes 16..31: order-3 dims.
    float termA, termB;
    if (lane < 16) {
        termA = 0.5f * (p1a * p1a - p2a);
        termB = 0.5f * (p1b * p1b - p2b);
    } else {
        termA = (p1a * p1a * p1a - 3.0f * p1a * p2a + 2.0f * p3a) * (1.0f / 6.0f);
        termB = (p1b * p1b * p1b - 3.0f * p1b * p2b + 2.0f * p3b) * (1.0f / 6.0f);
    }
    termA += linA;   // lanes 0..19 contribute linear part, others add 0
    termB += linB;

    // Warp-wide sums (two interleaved butterflies).
    #pragma unroll
    for (int o = 16; o > 0; o >>= 1) {
        termA += __shfl_xor_sync(0xffffffffu, termA, o);
        termB += __shfl_xor_sync(0xffffffffu, termB, o);
    }

    if (lane == 0) {
        const float b0 = __ldg(&bias[0]);
        out[sA] = termA + b0;
        out[sB] = termB + b0;
    }
}

extern "C" void kernel_launch(void* const* d_in, const int* in_sizes, int n_in,
                              void* d_out, int out_size)
{
    const int*   x    = (const int*)d_in[0];
    const float* emb  = (const float*)d_in[1];
    const float* lin  = (const float*)d_in[2];
    const float* bias = (const float*)d_in[3];
    float*       out  = (float*)d_out;

    // 16384 samples, 2 per warp, 8 warps/block -> 1024 blocks (single wave).
    const int threads = 256;
    const int blocks  = FM_BATCH / (2 * (threads / 32));
    fm_ho_kernel<<<blocks, threads>>>(x, emb, lin, bias, out);
}

// round 3
// speedup vs baseline: 1.0239x; 1.0239x over previous
#include <cuda_runtime.h>
#include <cstdint>

// HighOrderFactorizationMachineModel: BATCH=16384, F=20 fields (dim 50000 each),
// EMBED_DIM=16, ORDER=3. emb_table row = 32 floats: [0:16) order-2 dims,
// [16:32) order-3 dims. Closed forms via power sums (Newton identities):
//   e2 = (p1^2 - p2)/2
//   e3 = (p1^3 - 3 p1 p2 + 2 p3)/6
//
// One warp per sample, lane l owns row element l (one coalesced 128B line per
// gather). KEY CHANGE vs R2: indices and values are staged through explicit
// register arrays in SEPARATE unrolled loops so all 20 embedding gathers are
// independent and front-batched (MLP=20) instead of the shfl->LDG->FFMA
// serialized chain ptxas produced before (regs stuck at 32 = serialization).

#define FM_BATCH 16384
#define FM_F 20
#define FM_FIELD_DIM 50000

__global__ __launch_bounds__(256)
void fm_ho_kernel(const int* __restrict__ x,
                  const float* __restrict__ emb,
                  const float* __restrict__ lin,
                  const float* __restrict__ bias,
                  float* __restrict__ out)
{
    const int warp = (blockIdx.x * blockDim.x + threadIdx.x) >> 5;
    const int lane = threadIdx.x & 31;
    const int s = warp;

    // 1) All lanes load all 20 field indices (warp-uniform broadcast loads).
    int idx[FM_F];
    #pragma unroll
    for (int f = 0; f < FM_F; f++)
        idx[f] = __ldg(&x[s * FM_F + f]) + f * FM_FIELD_DIM;

    // 2) 20 independent gathers into live registers -> front-batched, MLP=20.
    float v[FM_F];
    #pragma unroll
    for (int f = 0; f < FM_F; f++)
        v[f] = __ldg(&emb[(long)idx[f] * 32 + lane]);

    // Linear-term gather rides on lanes 0..19 (x row is L1-hot by now).
    float linv = 0.0f;
    if (lane < FM_F)
        linv = __ldg(&lin[__ldg(&x[s * FM_F + lane]) + lane * FM_FIELD_DIM]);

    // 3) Power sums.
    float p1 = 0.0f, p2 = 0.0f, p3 = 0.0f;
    #pragma unroll
    for (int f = 0; f < FM_F; f++) {
        const float w = v[f];
        const float w2 = w * w;
        p1 += w;
        p2 += w2;
        p3 += w2 * w;
    }

    // Lanes 0..15: order-2 dims. Lanes 16..31: order-3 dims.
    float term;
    if (lane < 16) {
        term = 0.5f * (p1 * p1 - p2);
    } else {
        term = (p1 * p1 * p1 - 3.0f * p1 * p2 + 2.0f * p3) * (1.0f / 6.0f);
    }
    term += linv;   // lanes 0..19 contribute linear part, others add 0

    // Warp-wide sum.
    #pragma unroll
    for (int o = 16; o > 0; o >>= 1)
        term += __shfl_xor_sync(0xffffffffu, term, o);

    if (lane == 0)
        out[s] = term + __ldg(&bias[0]);
}

extern "C" void kernel_launch(void* const* d_in, const int* in_sizes, int n_in,
                              void* d_out, int out_size)
{
    const int*   x    = (const int*)d_in[0];
    const float* emb  = (const float*)d_in[1];
    const float* lin  = (const float*)d_in[2];
    const float* bias = (const float*)d_in[3];
    float*       out  = (float*)d_out;

    // 16384 samples, 1 warp each, 8 warps/block -> 2048 blocks.
    const int threads = 256;
    const int blocks  = (FM_BATCH * 32) / threads;
    fm_ho_kernel<<<blocks, threads>>>(x, emb, lin, bias, out);
}